// round 2
// baseline (speedup 1.0000x reference)
#include <cuda_runtime.h>
#include <math.h>

#define MAX_NODES 50000
#define IN_DIM 100
#define HID 16
#define NC 40

// Scratch (no allocations allowed): Y = X@W1, Z1 = A@Y, Z2 = A@relu(Z1)
__device__ float g_Y [MAX_NODES * HID];
__device__ float g_Z1[MAX_NODES * HID];
__device__ float g_Z2[MAX_NODES * HID];

// ---------------------------------------------------------------------------
// Zero the two accumulator buffers (atomics accumulate into them every call).
// ---------------------------------------------------------------------------
__global__ void zero_kernel(int n4) {
    int i = blockIdx.x * blockDim.x + threadIdx.x;
    if (i < n4) {
        ((float4*)g_Z1)[i] = make_float4(0.f, 0.f, 0.f, 0.f);
        ((float4*)g_Z2)[i] = make_float4(0.f, 0.f, 0.f, 0.f);
    }
}

// ---------------------------------------------------------------------------
// Y[n, 0:16] = features[n, 0:100] @ W1[100, 16]
// 16 lanes per node; W1 staged in shared. Feature reads are 4B broadcasts
// within each 16-lane group (L1-resident line reuse across k).
// ---------------------------------------------------------------------------
__global__ void gemm1_kernel(const float* __restrict__ X,
                             const float* __restrict__ W1, int N) {
    __shared__ float w[IN_DIM * HID];
    for (int i = threadIdx.x; i < IN_DIM * HID; i += blockDim.x) w[i] = W1[i];
    __syncthreads();
    int t = blockIdx.x * blockDim.x + threadIdx.x;
    int n = t >> 4, j = t & 15;
    if (n >= N) return;
    const float* xr = X + (long)n * IN_DIM;
    float acc = 0.f;
#pragma unroll 5
    for (int k = 0; k < IN_DIM; k++)
        acc += __ldg(xr + k) * w[k * HID + j];
    g_Y[n * HID + j] = acc;
}

// ---------------------------------------------------------------------------
// SpMM scatter: Z[dst] += val * (RELU? relu(X[src]) : X[src]), 16-dim rows.
// 4 threads per edge, each handles one float4 quad:
//   1x LDG.128 gather (L2-resident: X table is 3.2MB) + 1x red.global.v4.f32.
// FIRST selects which global buffers to use (symbols not addressable on host).
// ---------------------------------------------------------------------------
template <bool FIRST>
__global__ void spmm_kernel(const int* __restrict__ src,
                            const int* __restrict__ dst,
                            const float* __restrict__ val, int E) {
    int t = blockIdx.x * blockDim.x + threadIdx.x;
    int e = t >> 2;
    if (e >= E) return;
    int q = t & 3;
    const float* X = FIRST ? g_Y : g_Z1;
    float*       Z = FIRST ? g_Z1 : g_Z2;
    int s = __ldg(src + e);
    int d = __ldg(dst + e);
    float w = __ldg(val + e);
    float4 x = __ldg((const float4*)(X + s * HID) + q);
    if (!FIRST) {  // fused relu on layer-2 gather
        x.x = fmaxf(x.x, 0.f); x.y = fmaxf(x.y, 0.f);
        x.z = fmaxf(x.z, 0.f); x.w = fmaxf(x.w, 0.f);
    }
    float* zp = Z + d * HID + q * 4;  // 16B-aligned (row = 64B, quad = 16B)
    asm volatile("red.global.add.v4.f32 [%0], {%1, %2, %3, %4};"
                 :: "l"(zp), "f"(w * x.x), "f"(w * x.y),
                    "f"(w * x.z), "f"(w * x.w)
                 : "memory");
}

// ---------------------------------------------------------------------------
// out[n, 0:40] = log_softmax( Z2[n, 0:16] @ W2[16, 40] )
// One warp per node. Z2 row lives in lanes 0..15, broadcast via shuffles.
// Class c = lane for lanes 0..31, class 32+lane for lanes 0..7.
// ---------------------------------------------------------------------------
__global__ void out_kernel(const float* __restrict__ W2,
                           float* __restrict__ out, int N) {
    __shared__ float w[HID * NC];
    for (int i = threadIdx.x; i < HID * NC; i += blockDim.x) w[i] = W2[i];
    __syncthreads();
    int t = blockIdx.x * blockDim.x + threadIdx.x;
    int n = t >> 5, lane = t & 31;
    if (n >= N) return;
    float z = (lane < HID) ? g_Z2[n * HID + lane] : 0.f;
    float a0 = 0.f, a1 = 0.f;
    int c1 = (lane & 7) + 32;  // in-bounds read for all lanes; valid for lane<8
#pragma unroll
    for (int k = 0; k < HID; k++) {
        float zk = __shfl_sync(0xffffffffu, z, k);
        a0 += zk * w[k * NC + lane];
        a1 += zk * w[k * NC + c1];
    }
    float m = (lane < 8) ? fmaxf(a0, a1) : a0;
#pragma unroll
    for (int off = 16; off; off >>= 1)
        m = fmaxf(m, __shfl_xor_sync(0xffffffffu, m, off));
    float s = expf(a0 - m) + ((lane < 8) ? expf(a1 - m) : 0.f);
#pragma unroll
    for (int off = 16; off; off >>= 1)
        s += __shfl_xor_sync(0xffffffffu, s, off);
    float lse = m + logf(s);
    out[n * NC + lane] = a0 - lse;
    if (lane < 8) out[n * NC + 32 + lane] = a1 - lse;
}

// ---------------------------------------------------------------------------
extern "C" void kernel_launch(void* const* d_in, const int* in_sizes, int n_in,
                              void* d_out, int out_size) {
    const float* features = (const float*)d_in[0];
    const int*   esrc     = (const int*)  d_in[1];
    const int*   edst     = (const int*)  d_in[2];
    const float* evals    = (const float*)d_in[3];
    const float* W1       = (const float*)d_in[4];
    const float* W2       = (const float*)d_in[5];
    float*       out      = (float*)d_out;

    int N = in_sizes[0] / IN_DIM;   // 50000
    int E = in_sizes[1];            // 800000

    int n4 = N * HID / 4;
    zero_kernel<<<(n4 + 255) / 256, 256>>>(n4);
    gemm1_kernel<<<(N * HID + 255) / 256, 256>>>(features, W1, N);
    spmm_kernel<true ><<<((long)E * 4 + 255) / 256, 256>>>(esrc, edst, evals, E);
    spmm_kernel<false><<<((long)E * 4 + 255) / 256, 256>>>(esrc, edst, evals, E);
    out_kernel<<<((long)N * 32 + 255) / 256, 256>>>(W2, out, N);
}